// round 2
// baseline (speedup 1.0000x reference)
#include <cuda_runtime.h>
#include <math.h>

// ---------------- problem constants ----------------
#define BB     16          // batch
#define LL     64          // tokens
#define DD     256         // model dim
#define DINN   512         // inner dim
#define HH     8           // heads
#define DHH    64          // head dim
#define NSTATE 64          // ssm state
#define CD     640         // conv dim = DIN + 2*G*N
#define DPJ    1160        // in-proj width = 2*DIN + 2*G*N + H
#define NC     1000        // classes
#define EPSF   1e-6f
#define MROWS  (BB*LL)     // 1024

// ---------------- scratch (device globals; no allocation) ----------------
__device__ float g_p   [MROWS*768];
__device__ float g_pwT [768*DD];
__device__ float g_t   [MROWS*DD];
__device__ float g_nx  [MROWS*DD];
__device__ float g_zx  [2*MROWS*DPJ];         // per-direction in-proj outputs
__device__ float g_conv[2*MROWS*CD];
__device__ float g_dt  [2*MROWS*HH];
__device__ float g_y   [2*MROWS*DINN];
__device__ float g_yn  [MROWS*2*DINN];        // interleaved [row][dir*512+c] for fused out-proj
__device__ float g_tn  [MROWS*DD];
__device__ float g_mean[BB*DD];
__device__ float g_part[4*MROWS*DPJ];         // split-K partials (max use: inproj 4x1024x1160)

__device__ __forceinline__ int snake_idx(int l) {
    int r = l >> 3, c = l & 7;
    return (r & 1) ? (r * 8 + (7 - c)) : l;
}

// ---------------- patchify (snake order applied at gather) ----------------
__global__ void patchify_kernel(const float* __restrict__ x) {
    int idx = blockIdx.x * 256 + threadIdx.x;
    if (idx >= MROWS * 768) return;
    int j  = idx % 768;
    int bl = idx / 768;
    int l  = bl % LL;
    int b  = bl / LL;
    int ls = snake_idx(l);
    int gy = ls >> 3, gx = ls & 7;
    int ch = j >> 8;
    int py = (j >> 4) & 15;
    int px = j & 15;
    g_p[idx] = x[((b * 3 + ch) * 128 + gy * 16 + py) * 128 + gx * 16 + px];
}

__global__ void transpose_pw_kernel(const float* __restrict__ pw) {
    // pw: (256, 768) -> pwT: (768, 256)
    int idx = blockIdx.x * 256 + threadIdx.x;
    if (idx >= 768 * DD) return;
    int d = idx & 255;
    int j = idx >> 8;
    g_pwT[(size_t)j * DD + d] = pw[(size_t)d * 768 + j];
}

// ============================================================================
// Split-K batched SGEMM, 128x128 tile, 8x8 per thread, float4 smem traffic.
// Writes partial products: Cpart[z] = A_dir * B_chunk  (reduced later).
//   blockIdx.z -> dir = z / kchunks, kc = z % kchunks. Chunk K = KC = 128.
//   A (per dir): M x K row-major, A += dir*strideAdir
//   B row kg: (kg < splitAt) ? B0d + kg*N : B1 + (kg-splitAt)*N,
//     where B0d = dir ? Bb : Bf   (covers both dir-batched and K-concat cases)
// ============================================================================
#define KC 128
__global__ __launch_bounds__(256)
void gemm_sk_kernel(const float* __restrict__ A,
                    const float* __restrict__ Bf, const float* __restrict__ Bb,
                    const float* __restrict__ B1, int splitAt,
                    float* __restrict__ Cpart,
                    int N, int K, long strideAdir, int kchunks) {
    int z   = blockIdx.z;
    int dir = z / kchunks;
    int kc  = z - dir * kchunks;
    const float* B0 = dir ? Bb : Bf;
    A += (long)dir * strideAdir;
    float* C = Cpart + (long)z * MROWS * N;
    int kbase = kc * KC;

    __shared__ float As[16][128];
    __shared__ float Bs[16][128];
    int tid = threadIdx.x;
    int bm = blockIdx.y * 128, bn = blockIdx.x * 128;
    int tx = tid & 15, ty = tid >> 4;
    bool fullN = (bn + 128 <= N);

    float acc[8][8];
#pragma unroll
    for (int i = 0; i < 8; i++)
#pragma unroll
        for (int j = 0; j < 8; j++) acc[i][j] = 0.f;

    for (int k0 = 0; k0 < KC; k0 += 16) {
        // load A panel 128x16 (transposed into As[k][row])
#pragma unroll
        for (int q = 0; q < 2; q++) {
            int u = tid + q * 256;
            int r = u >> 2, kk = (u & 3) * 4;
            float4 a = *(const float4*)(A + (long)(bm + r) * K + kbase + k0 + kk);
            As[kk + 0][r] = a.x; As[kk + 1][r] = a.y;
            As[kk + 2][r] = a.z; As[kk + 3][r] = a.w;
        }
        // load B panel 16x128
#pragma unroll
        for (int q = 0; q < 2; q++) {
            int u = tid + q * 256;
            int kk = u >> 5, c = (u & 31) * 4;
            int kg = kbase + k0 + kk;
            const float* Brow = (kg < splitAt) ? (B0 + (long)kg * N)
                                               : (B1 + (long)(kg - splitAt) * N);
            if (fullN) {
                *(float4*)&Bs[kk][c] = *(const float4*)(Brow + bn + c);
            } else {
#pragma unroll
                for (int j = 0; j < 4; j++)
                    Bs[kk][c + j] = (bn + c + j < N) ? Brow[bn + c + j] : 0.f;
            }
        }
        __syncthreads();
#pragma unroll
        for (int k = 0; k < 16; k++) {
            float av[8], bv[8];
            *(float4*)&av[0] = *(const float4*)&As[k][ty * 8];
            *(float4*)&av[4] = *(const float4*)&As[k][ty * 8 + 4];
            *(float4*)&bv[0] = *(const float4*)&Bs[k][tx * 8];
            *(float4*)&bv[4] = *(const float4*)&Bs[k][tx * 8 + 4];
#pragma unroll
            for (int i = 0; i < 8; i++)
#pragma unroll
                for (int j = 0; j < 8; j++)
                    acc[i][j] = fmaf(av[i], bv[j], acc[i][j]);
        }
        __syncthreads();
    }

#pragma unroll
    for (int i = 0; i < 8; i++) {
        long row = bm + ty * 8 + i;
#pragma unroll
        for (int j = 0; j < 8; j++) {
            int col = bn + tx * 8 + j;
            if (col < N) C[row * N + col] = acc[i][j];
        }
    }
}

// generic partial reduce: dst = beta*dst + alpha * sum_z src[z*n + i]
__global__ void reduce_kernel(float* __restrict__ dst, const float* __restrict__ src,
                              int nz, long n, float alpha, float beta) {
    long i = (long)blockIdx.x * 256 + threadIdx.x;
    if (i >= n) return;
    float s = 0.f;
    for (int z = 0; z < nz; z++) s += src[(long)z * n + i];
    dst[i] = (beta == 0.f) ? alpha * s : fmaf(beta, dst[i], alpha * s);
}

// patch reduce: t = sum_z part + bias + pos(snake)
__global__ void patch_reduce_kernel(const float* __restrict__ src,
                                    const float* __restrict__ pb,
                                    const float* __restrict__ pos) {
    int idx = blockIdx.x * 256 + threadIdx.x;
    if (idx >= MROWS * DD) return;
    int d = idx & 255;
    int l = (idx >> 8) & 63;
    float s = 0.f;
#pragma unroll
    for (int z = 0; z < 6; z++) s += src[(long)z * MROWS * DD + idx];
    g_t[idx] = s + pb[d] + pos[snake_idx(l) * DD + d];
}

// ---------------- rmsnorm width 256 ----------------
__global__ void rmsnorm256_kernel(const float* __restrict__ in,
                                  const float* __restrict__ w,
                                  float* __restrict__ out) {
    int row = blockIdx.x, tid = threadIdx.x;
    float v = in[(size_t)row * DD + tid];
    float ss = v * v;
    __shared__ float red[8];
#pragma unroll
    for (int o = 16; o; o >>= 1) ss += __shfl_xor_sync(0xffffffffu, ss, o);
    if ((tid & 31) == 0) red[tid >> 5] = ss;
    __syncthreads();
    float tot = 0.f;
#pragma unroll
    for (int wq = 0; wq < 8; wq++) tot += red[wq];
    out[(size_t)row * DD + tid] = v * rsqrtf(tot * (1.f / DD) + EPSF) * w[tid];
}

// ---------------- conv (both dirs) + softplus(dt) ----------------
__global__ void convdt_kernel(const float* __restrict__ cw_f, const float* __restrict__ cw_b,
                              const float* __restrict__ cb_f, const float* __restrict__ cb_b,
                              const float* __restrict__ dtb_f, const float* __restrict__ dtb_b) {
    int idx = blockIdx.x * 256 + threadIdx.x;
    const int per = MROWS * (CD + HH);
    if (idx >= 2 * per) return;
    int dir = idx >= per;
    idx -= dir * per;
    int c  = idx % (CD + HH);
    int bl = idx / (CD + HH);
    int l  = bl % LL;
    int b  = bl / LL;
    const float* zx = g_zx + (long)dir * MROWS * DPJ;
    if (c < CD) {
        const float* cw = (dir ? cw_b : cw_f);
        float acc = (dir ? cb_b : cb_f)[c];
#pragma unroll
        for (int k = 0; k < 4; k++) {
            int ls = dir ? (l + 3 - k) : (l - 3 + k);
            if (ls >= 0 && ls < LL)
                acc = fmaf(cw[c * 4 + k], zx[((long)(b * LL + ls)) * DPJ + DINN + c], acc);
        }
        g_conv[(long)dir * MROWS * CD + (long)bl * CD + c] = acc / (1.f + expf(-acc));
    } else {
        int h = c - CD;
        float raw = zx[(long)bl * DPJ + DINN + CD + h] + (dir ? dtb_b : dtb_f)[h];
        g_dt[(long)dir * MROWS * HH + (long)bl * HH + h] =
            (raw > 20.f) ? raw : log1pf(expf(raw));
    }
}

// ---------------- SSM selective scan: one block per (dir,b,h) ----------------
__global__ __launch_bounds__(256)
void scan_kernel(const float* __restrict__ Alog_f, const float* __restrict__ Alog_b,
                 const float* __restrict__ Dp_f,  const float* __restrict__ Dp_b) {
    __shared__ float s_x[LL * DHH];
    __shared__ float s_B[LL * NSTATE];
    __shared__ float s_C[LL * NSTATE];
    int dir = blockIdx.x >> 7;
    int rem = blockIdx.x & 127;
    int b = rem >> 3, h = rem & 7;
    int tid = threadIdx.x;
    const float* base = g_conv + (long)dir * MROWS * CD + (long)b * LL * CD;
    for (int e = tid; e < LL * 64; e += 256) {
        int l = e >> 6, q = e & 63;
        const float* row = base + (long)l * CD;
        s_x[e] = row[h * DHH + q];
        s_B[e] = row[DINN + q];
        s_C[e] = row[DINN + NSTATE + q];
    }
    __syncthreads();

    int p  = tid >> 2;
    int n0 = (tid & 3) * 16;
    float nA  = -expf((dir ? Alog_b : Alog_f)[h]);
    float Dph = (dir ? Dp_b : Dp_f)[h];
    float hst[16];
#pragma unroll
    for (int j = 0; j < 16; j++) hst[j] = 0.f;

    const float* dtp = g_dt + (long)dir * MROWS * HH + (long)b * LL * HH + h;
    float* yout = g_y + (long)dir * MROWS * DINN + (long)b * LL * DINN + h * DHH + p;
    for (int s = 0; s < LL; s++) {
        int l = dir ? (LL - 1 - s) : s;
        float dtv = __ldg(dtp + l * HH);
        float dec = expf(nA * dtv);
        float xp  = s_x[l * 64 + p];
        float dtx = dtv * xp;
        float part = 0.f;
#pragma unroll
        for (int q4 = 0; q4 < 4; q4++) {
            float4 Bv = *(const float4*)&s_B[l * 64 + n0 + q4 * 4];
            float4 Cv = *(const float4*)&s_C[l * 64 + n0 + q4 * 4];
            float* hp = &hst[q4 * 4];
            hp[0] = fmaf(dec, hp[0], dtx * Bv.x); part = fmaf(hp[0], Cv.x, part);
            hp[1] = fmaf(dec, hp[1], dtx * Bv.y); part = fmaf(hp[1], Cv.y, part);
            hp[2] = fmaf(dec, hp[2], dtx * Bv.z); part = fmaf(hp[2], Cv.z, part);
            hp[3] = fmaf(dec, hp[3], dtx * Bv.w); part = fmaf(hp[3], Cv.w, part);
        }
        part += __shfl_xor_sync(0xffffffffu, part, 1);
        part += __shfl_xor_sync(0xffffffffu, part, 2);
        if ((tid & 3) == 0)
            yout[(long)l * DINN] = part + Dph * xp;
    }
}

// ---------------- gating + rmsnorm(512); writes K-interleaved layout ----------------
__global__ void gatenorm_kernel(const float* __restrict__ gn_f,
                                const float* __restrict__ gn_b) {
    int rowp = blockIdx.x;          // 0..2047
    int dir = rowp >> 10;
    int row = rowp & 1023;
    int tid = threadIdx.x;
    const float* gn = dir ? gn_b : gn_f;
    const float* zr = g_zx + (long)dir * MROWS * DPJ + (long)row * DPJ;
    const float* yr = g_y  + (long)dir * MROWS * DINN + (long)row * DINN;
    float z0 = zr[tid],       y0 = yr[tid];
    float z1 = zr[tid + 256], y1 = yr[tid + 256];
    float v0 = y0 * (z0 / (1.f + expf(-z0)));
    float v1 = y1 * (z1 / (1.f + expf(-z1)));
    float ss = v0 * v0 + v1 * v1;
    __shared__ float red[8];
#pragma unroll
    for (int o = 16; o; o >>= 1) ss += __shfl_xor_sync(0xffffffffu, ss, o);
    if ((tid & 31) == 0) red[tid >> 5] = ss;
    __syncthreads();
    float tot = 0.f;
#pragma unroll
    for (int wq = 0; wq < 8; wq++) tot += red[wq];
    float sc = rsqrtf(tot * (1.f / DINN) + EPSF);
    float* dst = g_yn + (long)row * (2 * DINN) + dir * DINN;
    dst[tid]       = v0 * sc * gn[tid];
    dst[tid + 256] = v1 * sc * gn[tid + 256];
}

// ---------------- mean over L ----------------
__global__ void meanl_kernel() {
    int b = blockIdx.x, d = threadIdx.x;
    float s = 0.f;
#pragma unroll 8
    for (int l = 0; l < LL; l++) s += g_tn[((long)(b * LL + l)) * DD + d];
    g_mean[b * DD + d] = s * (1.f / LL);
}

// ---------------- classifier head ----------------
__global__ void head_kernel(const float* __restrict__ hw,
                            const float* __restrict__ hb,
                            float* __restrict__ out) {
    __shared__ float sm[DD];
    int b = blockIdx.y;
    for (int c = threadIdx.x; c < DD; c += 256) sm[c] = g_mean[b * DD + c];
    __syncthreads();
    int cls = blockIdx.x * 256 + threadIdx.x;
    if (cls < NC) {
        float acc = hb[cls];
#pragma unroll 8
        for (int k = 0; k < DD; k++) acc = fmaf(sm[k], hw[k * NC + cls], acc);
        out[b * NC + cls] = acc;
    }
}

// ---------------- host launch ----------------
static float* symaddr(const void* sym) {
    void* p = nullptr;
    cudaGetSymbolAddress(&p, sym);
    return (float*)p;
}

extern "C" void kernel_launch(void* const* d_in, const int* in_sizes, int n_in,
                              void* d_out, int out_size) {
    const float* x       = (const float*)d_in[0];
    const float* patch_w = (const float*)d_in[1];
    const float* patch_b = (const float*)d_in[2];
    const float* pos     = (const float*)d_in[3];
    const float* norms_w = (const float*)d_in[4];
    const float* final_w = (const float*)d_in[5];
    const float* head_w  = (const float*)d_in[6];
    const float* head_b  = (const float*)d_in[7];
    const float* Win_f   = (const float*)d_in[8];
    const float* cw_f    = (const float*)d_in[9];
    const float* cb_f    = (const float*)d_in[10];
    const float* dtb_f   = (const float*)d_in[11];
    const float* Alog_f  = (const float*)d_in[12];
    const float* Dp_f    = (const float*)d_in[13];
    const float* gn_f    = (const float*)d_in[14];
    const float* Wout_f  = (const float*)d_in[15];
    const float* Win_b   = (const float*)d_in[16];
    const float* cw_b    = (const float*)d_in[17];
    const float* cb_b    = (const float*)d_in[18];
    const float* dtb_b   = (const float*)d_in[19];
    const float* Alog_b  = (const float*)d_in[20];
    const float* Dp_b    = (const float*)d_in[21];
    const float* gn_b    = (const float*)d_in[22];
    const float* Wout_b  = (const float*)d_in[23];
    float* out = (float*)d_out;

    float* p_p    = symaddr(g_p);
    float* p_pwT  = symaddr(g_pwT);
    float* p_t    = symaddr(g_t);
    float* p_nx   = symaddr(g_nx);
    float* p_zx   = symaddr(g_zx);
    float* p_yn   = symaddr(g_yn);
    float* p_tn   = symaddr(g_tn);
    float* p_part = symaddr(g_part);

    const int BIG = 1 << 30;
    const long MN_D   = (long)MROWS * DD;     // 262144
    const long MN_PJ  = (long)MROWS * DPJ;    // 1187840

    // ---- patch embed: p(1024x768) @ pwT(768x256), split-K 6 ----
    patchify_kernel<<<(MROWS * 768 + 255) / 256, 256>>>(x);
    transpose_pw_kernel<<<(768 * DD + 255) / 256, 256>>>(patch_w);
    gemm_sk_kernel<<<dim3(2, 8, 6), 256>>>(p_p, p_pwT, p_pwT, p_pwT, BIG,
                                           p_part, DD, 768, 0, 6);
    patch_reduce_kernel<<<(MROWS * DD + 255) / 256, 256>>>(p_part, patch_b, pos);

    const int convdt_blocks = (2 * MROWS * (CD + HH) + 255) / 256;

    for (int i = 0; i < 2; i++) {
        const float* Winf = Win_f  + (long)i * DD * DPJ;
        const float* Winb = Win_b  + (long)i * DD * DPJ;
        const float* Wof  = Wout_f + (long)i * DINN * DD;
        const float* Wob  = Wout_b + (long)i * DINN * DD;

        rmsnorm256_kernel<<<MROWS, 256>>>(p_t, norms_w + i * DD, p_nx);

        // in-proj both dirs, split-K 2: z = dir*2 + kc -> partials
        gemm_sk_kernel<<<dim3(10, 8, 4), 256>>>(p_nx, Winf, Winb, Winf, BIG,
                                                p_part, DPJ, DD, 0, 2);
        reduce_kernel<<<(int)((MN_PJ + 255) / 256), 256>>>(p_zx,          p_part,           2, MN_PJ, 1.f, 0.f);
        reduce_kernel<<<(int)((MN_PJ + 255) / 256), 256>>>(p_zx + MN_PJ,  p_part + 2*MN_PJ, 2, MN_PJ, 1.f, 0.f);

        convdt_kernel<<<convdt_blocks, 256>>>(cw_f + (long)i*CD*4, cw_b + (long)i*CD*4,
                                              cb_f + (long)i*CD,   cb_b + (long)i*CD,
                                              dtb_f + i*HH,        dtb_b + i*HH);
        scan_kernel<<<2 * BB * HH, 256>>>(Alog_f + i*HH, Alog_b + i*HH,
                                          Dp_f + i*HH,   Dp_b + i*HH);
        gatenorm_kernel<<<2 * MROWS, 256>>>(gn_f + (long)i*DINN, gn_b + (long)i*DINN);

        // fused out-proj: [yn_f | yn_b](1024x1024) @ [Wout_f; Wout_b](1024x256)
        // split-K 8, then t += 0.5 * sum(partials)
        gemm_sk_kernel<<<dim3(2, 8, 8), 256>>>(p_yn, Wof, Wof, Wob, DINN,
                                               p_part, DD, 2 * DINN, 0, 8);
        reduce_kernel<<<(int)((MN_D + 255) / 256), 256>>>(p_t, p_part, 8, MN_D, 0.5f, 1.f);
    }

    rmsnorm256_kernel<<<MROWS, 256>>>(p_t, final_w, p_tn);
    meanl_kernel<<<BB, 256>>>();
    head_kernel<<<dim3((NC + 255) / 256, BB), 256>>>(head_w, head_b, out);
}

// round 4
// speedup vs baseline: 1.3109x; 1.3109x over previous
#include <cuda_runtime.h>
#include <math.h>
#include <stdint.h>

// ---------------- problem constants ----------------
#define BB     16          // batch
#define LL     64          // tokens
#define DD     256         // model dim
#define DINN   512         // inner dim
#define HH     8           // heads
#define DHH    64          // head dim
#define NSTATE 64          // ssm state
#define CD     640         // conv dim = DIN + 2*G*N
#define DPJ    1160        // in-proj width = 2*DIN + 2*G*N + H
#define NC     1000        // classes
#define EPSF   1e-6f
#define MROWS  (BB*LL)     // 1024

// ---------------- scratch (device globals; no allocation) ----------------
__device__ float g_p   [MROWS*768];
__device__ float g_pwT [768*DD];
__device__ float g_t   [MROWS*DD];
__device__ float g_nx  [MROWS*DD];
__device__ float g_zx  [2*MROWS*DPJ];         // per-direction in-proj outputs
__device__ float g_conv[2*MROWS*CD];
__device__ float g_dt  [2*MROWS*HH];
__device__ float g_y   [2*MROWS*DINN];
__device__ float g_yn  [MROWS*2*DINN];        // interleaved [row][dir*512+c] for fused out-proj
__device__ float g_tn  [MROWS*DD];
__device__ float g_mean[BB*DD];
__device__ float g_part[4*MROWS*DPJ];         // split-K partials

__device__ __forceinline__ int snake_idx(int l) {
    int r = l >> 3, c = l & 7;
    return (r & 1) ? (r * 8 + (7 - c)) : l;
}

// ---------------- patchify (snake order applied at gather) ----------------
__global__ void patchify_kernel(const float* __restrict__ x) {
    int idx = blockIdx.x * 256 + threadIdx.x;
    if (idx >= MROWS * 768) return;
    int j  = idx % 768;
    int bl = idx / 768;
    int l  = bl % LL;
    int b  = bl / LL;
    int ls = snake_idx(l);
    int gy = ls >> 3, gx = ls & 7;
    int ch = j >> 8;
    int py = (j >> 4) & 15;
    int px = j & 15;
    g_p[idx] = x[((b * 3 + ch) * 128 + gy * 16 + py) * 128 + gx * 16 + px];
}

__global__ void transpose_pw_kernel(const float* __restrict__ pw) {
    // pw: (256, 768) -> pwT: (768, 256)
    int idx = blockIdx.x * 256 + threadIdx.x;
    if (idx >= 768 * DD) return;
    int d = idx & 255;
    int j = idx >> 8;
    g_pwT[(size_t)j * DD + d] = pw[(size_t)d * 768 + j];
}

// ============================================================================
// 3xTF32 tensor-core GEMM (fp32-accurate via Dekker split).
// Block tile 128x128, 8 warps as 2(m) x 4(n), warp tile 64x32.
// Split-K batched: blockIdx.z -> dir = z/kchunks, kc = z%kchunks, chunk Kc.
//   A (per dir): M x K row-major, A += dir*strideAdir
//   B row kg: (kg < splitAt) ? B0d + kg*N : B1 + (kg-splitAt)*N,
//     B0d = dir ? Bb : Bf.
//   Cpart[z] gets the partial (alpha=1); reduced by consumers.
// ============================================================================
#define SMS 132   // smem row stride (floats)

__device__ __forceinline__ void tf32_split(float x, float& h, float& l) {
    float hh = __uint_as_float(__float_as_uint(x) & 0xffffe000u);
    h = hh;
    l = __uint_as_float(__float_as_uint(x - hh) & 0xffffe000u);
}

__device__ __forceinline__ void mma_tf32(float4& c, uint32_t a0, uint32_t a1,
                                         uint32_t a2, uint32_t a3,
                                         uint32_t b0, uint32_t b1) {
    asm volatile(
        "mma.sync.aligned.m16n8k8.row.col.f32.tf32.tf32.f32 "
        "{%0,%1,%2,%3}, {%4,%5,%6,%7}, {%8,%9}, {%0,%1,%2,%3};\n"
        : "+f"(c.x), "+f"(c.y), "+f"(c.z), "+f"(c.w)
        : "r"(a0), "r"(a1), "r"(a2), "r"(a3), "r"(b0), "r"(b1));
}

__global__ __launch_bounds__(256)
void gemm_tf32_kernel(const float* __restrict__ A,
                      const float* __restrict__ Bf, const float* __restrict__ Bb,
                      const float* __restrict__ B1, int splitAt,
                      float* __restrict__ Cpart,
                      int N, int K, long strideAdir, int kchunks, int Kc) {
    __shared__ float As_h[16][SMS];
    __shared__ float As_l[16][SMS];
    __shared__ float Bs_h[16][SMS];
    __shared__ float Bs_l[16][SMS];

    int z   = blockIdx.z;
    int dir = z / kchunks;
    int kc  = z - dir * kchunks;
    const float* B0 = dir ? Bb : Bf;
    A += (long)dir * strideAdir;
    float* C = Cpart + (long)z * MROWS * N;
    int kbase = kc * Kc;

    int tid  = threadIdx.x;
    int lane = tid & 31;
    int warp = tid >> 5;
    int wm   = warp >> 2;       // 0..1
    int wn   = warp & 3;        // 0..3
    int g    = lane >> 2;       // 0..7
    int t    = lane & 3;        // 0..3
    int bm = blockIdx.y * 128, bn = blockIdx.x * 128;
    bool fullN = (bn + 128 <= N);

    float4 acc[4][4];
#pragma unroll
    for (int i = 0; i < 4; i++)
#pragma unroll
        for (int j = 0; j < 4; j++) acc[i][j] = make_float4(0.f, 0.f, 0.f, 0.f);

#pragma unroll 1
    for (int k0 = 0; k0 < Kc; k0 += 16) {
        // ---- load + split A panel 128x16 into As[k][m] ----
#pragma unroll
        for (int q = 0; q < 2; q++) {
            int u  = tid + q * 256;
            int r  = u >> 2;
            int k4 = (u & 3) * 4;
            float4 v = *(const float4*)(A + (long)(bm + r) * K + kbase + k0 + k4);
            float h, l;
            tf32_split(v.x, h, l); As_h[k4 + 0][r] = h; As_l[k4 + 0][r] = l;
            tf32_split(v.y, h, l); As_h[k4 + 1][r] = h; As_l[k4 + 1][r] = l;
            tf32_split(v.z, h, l); As_h[k4 + 2][r] = h; As_l[k4 + 2][r] = l;
            tf32_split(v.w, h, l); As_h[k4 + 3][r] = h; As_l[k4 + 3][r] = l;
        }
        // ---- load + split B panel 16x128 into Bs[k][n] ----
#pragma unroll
        for (int q = 0; q < 2; q++) {
            int u  = tid + q * 256;
            int kk = u >> 5;
            int n4 = (u & 31) * 4;
            int kg = kbase + k0 + kk;
            const float* Brow = (kg < splitAt) ? (B0 + (long)kg * N)
                                               : (B1 + (long)(kg - splitAt) * N);
            float h, l;
            if (fullN) {
                float4 v = *(const float4*)(Brow + bn + n4);
                tf32_split(v.x, h, l); Bs_h[kk][n4 + 0] = h; Bs_l[kk][n4 + 0] = l;
                tf32_split(v.y, h, l); Bs_h[kk][n4 + 1] = h; Bs_l[kk][n4 + 1] = l;
                tf32_split(v.z, h, l); Bs_h[kk][n4 + 2] = h; Bs_l[kk][n4 + 2] = l;
                tf32_split(v.w, h, l); Bs_h[kk][n4 + 3] = h; Bs_l[kk][n4 + 3] = l;
            } else {
#pragma unroll
                for (int j = 0; j < 4; j++) {
                    float v = (bn + n4 + j < N) ? Brow[bn + n4 + j] : 0.f;
                    tf32_split(v, h, l);
                    Bs_h[kk][n4 + j] = h;
                    Bs_l[kk][n4 + j] = l;
                }
            }
        }
        __syncthreads();

#pragma unroll
        for (int s = 0; s < 2; s++) {
            int k8 = s * 8;
            int kr0 = k8 + t, kr1 = k8 + t + 4;
            // preload B fragments for 4 n8-tiles
            uint32_t bh0[4], bh1[4], bl0[4], bl1[4];
#pragma unroll
            for (int nt = 0; nt < 4; nt++) {
                int n = wn * 32 + nt * 8 + g;
                bh0[nt] = __float_as_uint(Bs_h[kr0][n]);
                bh1[nt] = __float_as_uint(Bs_h[kr1][n]);
                bl0[nt] = __float_as_uint(Bs_l[kr0][n]);
                bl1[nt] = __float_as_uint(Bs_l[kr1][n]);
            }
#pragma unroll
            for (int mt = 0; mt < 4; mt++) {
                int m0 = wm * 64 + mt * 16 + g;
                uint32_t ah0 = __float_as_uint(As_h[kr0][m0]);
                uint32_t ah1 = __float_as_uint(As_h[kr0][m0 + 8]);
                uint32_t ah2 = __float_as_uint(As_h[kr1][m0]);
                uint32_t ah3 = __float_as_uint(As_h[kr1][m0 + 8]);
                uint32_t al0 = __float_as_uint(As_l[kr0][m0]);
                uint32_t al1 = __float_as_uint(As_l[kr0][m0 + 8]);
                uint32_t al2 = __float_as_uint(As_l[kr1][m0]);
                uint32_t al3 = __float_as_uint(As_l[kr1][m0 + 8]);
#pragma unroll
                for (int nt = 0; nt < 4; nt++) {
                    mma_tf32(acc[mt][nt], ah0, ah1, ah2, ah3, bh0[nt], bh1[nt]);
                    mma_tf32(acc[mt][nt], ah0, ah1, ah2, ah3, bl0[nt], bl1[nt]);
                    mma_tf32(acc[mt][nt], al0, al1, al2, al3, bh0[nt], bh1[nt]);
                }
            }
        }
        __syncthreads();
    }

    // ---- epilogue: write partial ----
#pragma unroll
    for (int mt = 0; mt < 4; mt++) {
        long row0 = bm + wm * 64 + mt * 16 + g;
        long row1 = row0 + 8;
#pragma unroll
        for (int nt = 0; nt < 4; nt++) {
            int col = bn + wn * 32 + nt * 8 + 2 * t;
            if (col < N) {
                float4 c = acc[mt][nt];
                *(float2*)&C[row0 * N + col] = make_float2(c.x, c.y);
                *(float2*)&C[row1 * N + col] = make_float2(c.z, c.w);
            }
        }
    }
}

// patch reduce: t = sum_z part + bias + pos(snake)
__global__ void patch_reduce_kernel(const float* __restrict__ src,
                                    const float* __restrict__ pb,
                                    const float* __restrict__ pos) {
    int idx = blockIdx.x * 256 + threadIdx.x;
    if (idx >= MROWS * DD) return;
    int d = idx & 255;
    int l = (idx >> 8) & 63;
    float s = 0.f;
#pragma unroll
    for (int z = 0; z < 6; z++) s += src[(long)z * MROWS * DD + idx];
    g_t[idx] = s + pb[d] + pos[snake_idx(l) * DD + d];
}

// ---------------- rmsnorm width 256 ----------------
__global__ void rmsnorm256_kernel(const float* __restrict__ in,
                                  const float* __restrict__ w,
                                  float* __restrict__ out) {
    int row = blockIdx.x, tid = threadIdx.x;
    float v = in[(size_t)row * DD + tid];
    float ss = v * v;
    __shared__ float red[8];
#pragma unroll
    for (int o = 16; o; o >>= 1) ss += __shfl_xor_sync(0xffffffffu, ss, o);
    if ((tid & 31) == 0) red[tid >> 5] = ss;
    __syncthreads();
    float tot = 0.f;
#pragma unroll
    for (int wq = 0; wq < 8; wq++) tot += red[wq];
    out[(size_t)row * DD + tid] = v * rsqrtf(tot * (1.f / DD) + EPSF) * w[tid];
}

// ---------------- fused: t += 0.5*sum_8(partials); out = rmsnorm(t)*w ----------------
__global__ void residual_norm_kernel(const float* __restrict__ src,
                                     const float* __restrict__ w,
                                     float* __restrict__ out) {
    int row = blockIdx.x, tid = threadIdx.x;
    long idx = (long)row * DD + tid;
    float s = 0.f;
#pragma unroll
    for (int z = 0; z < 8; z++) s += src[(long)z * MROWS * DD + idx];
    float v = fmaf(0.5f, s, g_t[idx]);
    g_t[idx] = v;
    float ss = v * v;
    __shared__ float red[8];
#pragma unroll
    for (int o = 16; o; o >>= 1) ss += __shfl_xor_sync(0xffffffffu, ss, o);
    if ((tid & 31) == 0) red[tid >> 5] = ss;
    __syncthreads();
    float tot = 0.f;
#pragma unroll
    for (int wq = 0; wq < 8; wq++) tot += red[wq];
    out[idx] = v * rsqrtf(tot * (1.f / DD) + EPSF) * w[tid];
}

// ---------------- conv (both dirs) + softplus(dt) ----------------
__global__ void convdt_kernel(const float* __restrict__ cw_f, const float* __restrict__ cw_b,
                              const float* __restrict__ cb_f, const float* __restrict__ cb_b,
                              const float* __restrict__ dtb_f, const float* __restrict__ dtb_b) {
    int idx = blockIdx.x * 256 + threadIdx.x;
    const int per = MROWS * (CD + HH);
    if (idx >= 2 * per) return;
    int dir = idx >= per;
    idx -= dir * per;
    int c  = idx % (CD + HH);
    int bl = idx / (CD + HH);
    int l  = bl % LL;
    int b  = bl / LL;
    const float* zx = g_zx + (long)dir * MROWS * DPJ;
    if (c < CD) {
        const float* cw = (dir ? cw_b : cw_f);
        float acc = (dir ? cb_b : cb_f)[c];
#pragma unroll
        for (int k = 0; k < 4; k++) {
            int ls = dir ? (l + 3 - k) : (l - 3 + k);
            if (ls >= 0 && ls < LL)
                acc = fmaf(cw[c * 4 + k], zx[((long)(b * LL + ls)) * DPJ + DINN + c], acc);
        }
        g_conv[(long)dir * MROWS * CD + (long)bl * CD + c] = acc / (1.f + expf(-acc));
    } else {
        int h = c - CD;
        float raw = zx[(long)bl * DPJ + DINN + CD + h] + (dir ? dtb_b : dtb_f)[h];
        g_dt[(long)dir * MROWS * HH + (long)bl * HH + h] =
            (raw > 20.f) ? raw : log1pf(expf(raw));
    }
}

// ---------------- SSM selective scan: one block per (dir,b,h) ----------------
__global__ __launch_bounds__(256)
void scan_kernel(const float* __restrict__ Alog_f, const float* __restrict__ Alog_b,
                 const float* __restrict__ Dp_f,  const float* __restrict__ Dp_b) {
    __shared__ float s_x[LL * DHH];
    __shared__ float s_B[LL * NSTATE];
    __shared__ float s_C[LL * NSTATE];
    int dir = blockIdx.x >> 7;
    int rem = blockIdx.x & 127;
    int b = rem >> 3, h = rem & 7;
    int tid = threadIdx.x;
    const float* base = g_conv + (long)dir * MROWS * CD + (long)b * LL * CD;
    for (int e = tid; e < LL * 64; e += 256) {
        int l = e >> 6, q = e & 63;
        const float* row = base + (long)l * CD;
        s_x[e] = row[h * DHH + q];
        s_B[e] = row[DINN + q];
        s_C[e] = row[DINN + NSTATE + q];
    }
    __syncthreads();

    int p  = tid >> 2;
    int n0 = (tid & 3) * 16;
    float nA  = -expf((dir ? Alog_b : Alog_f)[h]);
    float Dph = (dir ? Dp_b : Dp_f)[h];
    float hst[16];
#pragma unroll
    for (int j = 0; j < 16; j++) hst[j] = 0.f;

    const float* dtp = g_dt + (long)dir * MROWS * HH + (long)b * LL * HH + h;
    float* yout = g_y + (long)dir * MROWS * DINN + (long)b * LL * DINN + h * DHH + p;
    for (int s = 0; s < LL; s++) {
        int l = dir ? (LL - 1 - s) : s;
        float dtv = __ldg(dtp + l * HH);
        float dec = expf(nA * dtv);
        float xp  = s_x[l * 64 + p];
        float dtx = dtv * xp;
        float part = 0.f;
#pragma unroll
        for (int q4 = 0; q4 < 4; q4++) {
            float4 Bv = *(const float4*)&s_B[l * 64 + n0 + q4 * 4];
            float4 Cv = *(const float4*)&s_C[l * 64 + n0 + q4 * 4];
            float* hp = &hst[q4 * 4];
            hp[0] = fmaf(dec, hp[0], dtx * Bv.x); part = fmaf(hp[0], Cv.x, part);
            hp[1] = fmaf(dec, hp[1], dtx * Bv.y); part = fmaf(hp[1], Cv.y, part);
            hp[2] = fmaf(dec, hp[2], dtx * Bv.z); part = fmaf(hp[2], Cv.z, part);
            hp[3] = fmaf(dec, hp[3], dtx * Bv.w); part = fmaf(hp[3], Cv.w, part);
        }
        part += __shfl_xor_sync(0xffffffffu, part, 1);
        part += __shfl_xor_sync(0xffffffffu, part, 2);
        if ((tid & 3) == 0)
            yout[(long)l * DINN] = part + Dph * xp;
    }
}

// ---------------- gating + rmsnorm(512); writes K-interleaved layout ----------------
__global__ void gatenorm_kernel(const float* __restrict__ gn_f,
                                const float* __restrict__ gn_b) {
    int rowp = blockIdx.x;          // 0..2047
    int dir = rowp >> 10;
    int row = rowp & 1023;
    int tid = threadIdx.x;
    const float* gn = dir ? gn_b : gn_f;
    const float* zr = g_zx + (long)dir * MROWS * DPJ + (long)row * DPJ;
    const float* yr = g_y  + (long)dir * MROWS * DINN + (long)row * DINN;
    float z0 = zr[tid],       y0 = yr[tid];
    float z1 = zr[tid + 256], y1 = yr[tid + 256];
    float v0 = y0 * (z0 / (1.f + expf(-z0)));
    float v1 = y1 * (z1 / (1.f + expf(-z1)));
    float ss = v0 * v0 + v1 * v1;
    __shared__ float red[8];
#pragma unroll
    for (int o = 16; o; o >>= 1) ss += __shfl_xor_sync(0xffffffffu, ss, o);
    if ((tid & 31) == 0) red[tid >> 5] = ss;
    __syncthreads();
    float tot = 0.f;
#pragma unroll
    for (int wq = 0; wq < 8; wq++) tot += red[wq];
    float sc = rsqrtf(tot * (1.f / DINN) + EPSF);
    float* dst = g_yn + (long)row * (2 * DINN) + dir * DINN;
    dst[tid]       = v0 * sc * gn[tid];
    dst[tid + 256] = v1 * sc * gn[tid + 256];
}

// ---------------- mean over L ----------------
__global__ void meanl_kernel() {
    int b = blockIdx.x, d = threadIdx.x;
    float s = 0.f;
#pragma unroll 8
    for (int l = 0; l < LL; l++) s += g_tn[((long)(b * LL + l)) * DD + d];
    g_mean[b * DD + d] = s * (1.f / LL);
}

// ---------------- classifier head ----------------
__global__ void head_kernel(const float* __restrict__ hw,
                            const float* __restrict__ hb,
                            float* __restrict__ out) {
    __shared__ float sm[DD];
    int b = blockIdx.y;
    for (int c = threadIdx.x; c < DD; c += 256) sm[c] = g_mean[b * DD + c];
    __syncthreads();
    int cls = blockIdx.x * 256 + threadIdx.x;
    if (cls < NC) {
        float acc = hb[cls];
#pragma unroll 8
        for (int k = 0; k < DD; k++) acc = fmaf(sm[k], hw[k * NC + cls], acc);
        out[b * NC + cls] = acc;
    }
}

// ---------------- host launch ----------------
static float* symaddr(const void* sym) {
    void* p = nullptr;
    cudaGetSymbolAddress(&p, sym);
    return (float*)p;
}

extern "C" void kernel_launch(void* const* d_in, const int* in_sizes, int n_in,
                              void* d_out, int out_size) {
    const float* x       = (const float*)d_in[0];
    const float* patch_w = (const float*)d_in[1];
    const float* patch_b = (const float*)d_in[2];
    const float* pos     = (const float*)d_in[3];
    const float* norms_w = (const float*)d_in[4];
    const float* final_w = (const float*)d_in[5];
    const float* head_w  = (const float*)d_in[6];
    const float* head_b  = (const float*)d_in[7];
    const float* Win_f   = (const float*)d_in[8];
    const float* cw_f    = (const float*)d_in[9];
    const float* cb_f    = (const float*)d_in[10];
    const float* dtb_f   = (const float*)d_in[11];
    const float* Alog_f  = (const float*)d_in[12];
    const float* Dp_f    = (const float*)d_in[13];
    const float* gn_f    = (const float*)d_in[14];
    const float* Wout_f  = (const float*)d_in[15];
    const float* Win_b   = (const float*)d_in[16];
    const float* cw_b    = (const float*)d_in[17];
    const float* cb_b    = (const float*)d_in[18];
    const float* dtb_b   = (const float*)d_in[19];
    const float* Alog_b  = (const float*)d_in[20];
    const float* Dp_b    = (const float*)d_in[21];
    const float* gn_b    = (const float*)d_in[22];
    const float* Wout_b  = (const float*)d_in[23];
    float* out = (float*)d_out;

    float* p_p    = symaddr(g_p);
    float* p_pwT  = symaddr(g_pwT);
    float* p_t    = symaddr(g_t);
    float* p_nx   = symaddr(g_nx);
    float* p_zx   = symaddr(g_zx);
    float* p_yn   = symaddr(g_yn);
    float* p_tn   = symaddr(g_tn);
    float* p_part = symaddr(g_part);

    const int BIG = 1 << 30;

    // ---- patch embed: p(1024x768) @ pwT(768x256), split-K 6 ----
    patchify_kernel<<<(MROWS * 768 + 255) / 256, 256>>>(x);
    transpose_pw_kernel<<<(768 * DD + 255) / 256, 256>>>(patch_w);
    gemm_tf32_kernel<<<dim3(2, 8, 6), 256>>>(p_p, p_pwT, p_pwT, p_pwT, BIG,
                                             p_part, DD, 768, 0, 6, 128);
    patch_reduce_kernel<<<(MROWS * DD + 255) / 256, 256>>>(p_part, patch_b, pos);

    // first pre-norm (from fresh t)
    rmsnorm256_kernel<<<MROWS, 256>>>(p_t, norms_w, p_nx);

    const int convdt_blocks = (2 * MROWS * (CD + HH) + 255) / 256;

    for (int i = 0; i < 2; i++) {
        const float* Winf = Win_f  + (long)i * DD * DPJ;
        const float* Winb = Win_b  + (long)i * DD * DPJ;
        const float* Wof  = Wout_f + (long)i * DINN * DD;
        const float* Wob  = Wout_b + (long)i * DINN * DD;

        // in-proj both dirs, no split-K (grid z = dir), writes g_zx directly
        gemm_tf32_kernel<<<dim3(10, 8, 2), 256>>>(p_nx, Winf, Winb, Winf, BIG,
                                                  p_zx, DPJ, DD, 0, 1, DD);

        convdt_kernel<<<convdt_blocks, 256>>>(cw_f + (long)i*CD*4, cw_b + (long)i*CD*4,
                                              cb_f + (long)i*CD,   cb_b + (long)i*CD,
                                              dtb_f + i*HH,        dtb_b + i*HH);
        scan_kernel<<<2 * BB * HH, 256>>>(Alog_f + i*HH, Alog_b + i*HH,
                                          Dp_f + i*HH,   Dp_b + i*HH);
        gatenorm_kernel<<<2 * MROWS, 256>>>(gn_f + (long)i*DINN, gn_b + (long)i*DINN);

        // fused out-proj: [yn_f | yn_b](1024x1024) @ [Wout_f; Wout_b](1024x256)
        // split-K 8 -> partials
        gemm_tf32_kernel<<<dim3(2, 8, 8), 256>>>(p_yn, Wof, Wof, Wob, DINN,
                                                 p_part, DD, 2 * DINN, 0, 8, 128);
        // fused: t += 0.5*sum(partials); next-norm
        if (i == 0)
            residual_norm_kernel<<<MROWS, 256>>>(p_part, norms_w + DD, p_nx);
        else
            residual_norm_kernel<<<MROWS, 256>>>(p_part, final_w, p_tn);
    }

    meanl_kernel<<<BB, 256>>>();
    head_kernel<<<dim3((NC + 255) / 256, BB), 256>>>(head_w, head_b, out);
}